// round 2
// baseline (speedup 1.0000x reference)
#include <cuda_runtime.h>
#include <cuda_bf16.h>

// MLPAttention: B=4, N=512, KLEN=512, D=64, TAU=4
//   Wq = W1[0::2], Wk = W1[1::2]
//   hq = Q@Wq + b1, hk = K@Wk
//   res[n,k] = sum_e relu(hq[n,e]+hk[k,e]) * W2[e]   (b2 cancels in softmax)
//   att = softmax(res/TAU), out = att@V
// Outputs: out (B*N*D) then att (B*N*K), concatenated.

#define BB 4
#define NN 512
#define KL 512
#define DD 64

typedef unsigned long long ull;

__device__ float g_hq[BB * NN * DD];    // [row][e]
__device__ float g_hkT[BB * DD * KL];   // [b][e][k]

// ---------- packed f32x2 helpers ----------
__device__ __forceinline__ ull pk2(float x, float y) {
    ull r; asm("mov.b64 %0, {%1, %2};" : "=l"(r) : "f"(x), "f"(y)); return r;
}
__device__ __forceinline__ float2 up2(ull u) {
    float2 f; asm("mov.b64 {%0, %1}, %2;" : "=f"(f.x), "=f"(f.y) : "l"(u)); return f;
}
__device__ __forceinline__ ull fadd2(ull a, ull b) {
    ull r; asm("add.rn.f32x2 %0, %1, %2;" : "=l"(r) : "l"(a), "l"(b)); return r;
}
__device__ __forceinline__ ull ffma2(ull a, ull b, ull c) {
    ull r; asm("fma.rn.f32x2 %0, %1, %2, %3;" : "=l"(r) : "l"(a), "l"(b), "l"(c)); return r;
}

// ---------- Kernel A (fused): hq = Q@Wq + b1  and  hkT = (K@Wk)^T ----------
// blocks [0,512): hq, 4 rows/block.  blocks [512,1024): hkT.
__global__ __launch_bounds__(256) void kA(const float* __restrict__ Q,
                                          const float* __restrict__ K,
                                          const float* __restrict__ W1,
                                          const float* __restrict__ b1,
                                          float* __restrict__ hq,
                                          float* __restrict__ hkT) {
    int t = threadIdx.x;
    if (blockIdx.x < 512) {
        __shared__ float Qs[4 * 64];
        int r0 = blockIdx.x * 4;
        Qs[t] = Q[r0 * 64 + t];
        __syncthreads();
        int rl = t >> 6, e = t & 63;
        float acc = b1[e];
#pragma unroll
        for (int d = 0; d < 64; d++)
            acc = fmaf(Qs[rl * 64 + d], __ldg(&W1[d * 128 + e]), acc);   // W1[2d][e]
        hq[(r0 + rl) * 64 + e] = acc;
    } else {
        __shared__ float Ks[64 * 65];
        int bid = blockIdx.x - 512;
        int b = bid >> 7;
        int kt = (bid >> 4) & 7;
        int et = bid & 15;
#pragma unroll
        for (int j = 0; j < 16; j++) {
            int idx = t + 256 * j;
            int kk = idx >> 6, d = idx & 63;
            Ks[kk * 65 + d] = K[(b * 512 + kt * 64 + kk) * 64 + d];
        }
        __syncthreads();
        int el = t >> 6, kl = t & 63;
        int e = et * 4 + el;
        float acc = 0.f;
#pragma unroll
        for (int d = 0; d < 64; d++)
            acc = fmaf(Ks[kl * 65 + d], __ldg(&W1[d * 128 + 64 + e]), acc);  // W1[2d+1][e]
        hkT[b * (64 * 512) + e * 512 + kt * 64 + kl] = acc;
    }
}

// ---------- Kernel BC (fused): res -> softmax -> att, out = att@V ----------
// grid 128 (b x 32 n-tiles of 16), 512 threads.
// smem union S[9344] floats:
//   phase1:  res_s = S[0..8192)  [16 rows][512 k]
//            hq_f  = S[8192..9216)  [64 e][16 i]
//            w2s   = S[9216..9344)  (64 x {w,w} ull)
//   after softmax: att2 = S[0..9216) as [k][18]: float idx k*18 + row
//   phase3 reduce: red  = S[0..8192) as ull [split][512]
__global__ __launch_bounds__(512) void kBC(const float* __restrict__ hq,
                                           const float* __restrict__ hkT,
                                           const float* __restrict__ W2,
                                           const float* __restrict__ V,
                                           float* __restrict__ att,
                                           float* __restrict__ out) {
    __shared__ __align__(16) float S[9344];
    float* res_s = S;
    float* hq_f  = S + 8192;
    ull*   w2s   = (ull*)(S + 9216);

    int b  = blockIdx.x >> 5;
    int n0 = (blockIdx.x & 31) << 4;
    int t  = threadIdx.x;

    {   // stage hq tile: hq_f[e][j] = hq[n0+j][e], j = 0..15
        int i = t >> 6, e = t & 63;
        hq_f[e * 16 + i]     = hq[(b * 512 + n0 + i) * 64 + e];
        hq_f[e * 16 + i + 8] = hq[(b * 512 + n0 + i + 8) * 64 + e];
    }
    if (t < 64) { float w = W2[t]; w2s[t] = pk2(w, w); }
    __syncthreads();

    // ---- phase 1: res[n,k] for this thread's k-column (t) ----
    const float4* hq4 = (const float4*)hq_f;         // [e][4] — 2 n-pairs per float4
    const float*  hkb = hkT + b * (64 * 512) + t;

    ull acc[8];
#pragma unroll
    for (int p = 0; p < 8; p++) acc[p] = 0ull;

#pragma unroll 8
    for (int e = 0; e < 64; e++) {
        float hkv = __ldg(hkb + e * 512);            // coalesced, L2-resident
        ull hk2 = pk2(hkv, hkv);
        ull w2e = w2s[e];
#pragma unroll
        for (int q = 0; q < 4; q++) {
            float4 h = hq4[e * 4 + q];               // LDS.128: pairs 2q, 2q+1
            float2 s0 = up2(fadd2(pk2(h.x, h.y), hk2));
            float2 s1 = up2(fadd2(pk2(h.z, h.w), hk2));
            acc[2 * q]     = ffma2(pk2(fmaxf(s0.x, 0.f), fmaxf(s0.y, 0.f)), w2e, acc[2 * q]);
            acc[2 * q + 1] = ffma2(pk2(fmaxf(s1.x, 0.f), fmaxf(s1.y, 0.f)), w2e, acc[2 * q + 1]);
        }
    }
#pragma unroll
    for (int p = 0; p < 8; p++) {
        float2 a = up2(acc[p]);
        res_s[(2 * p) * 512 + t]     = a.x;
        res_s[(2 * p + 1) * 512 + t] = a.y;
    }
    __syncthreads();

    // ---- phase 2: softmax, warp w owns row n0+w ----
    int w = t >> 5, lane = t & 31;
    float v[16], m = -1e30f;
#pragma unroll
    for (int i = 0; i < 16; i++) {
        v[i] = res_s[w * 512 + lane + 32 * i];
        m = fmaxf(m, v[i]);
    }
#pragma unroll
    for (int o = 16; o; o >>= 1) m = fmaxf(m, __shfl_xor_sync(0xffffffffu, m, o));
    float sum = 0.f;
#pragma unroll
    for (int i = 0; i < 16; i++) {
        v[i] = __expf((v[i] - m) * 0.25f);           // /TAU
        sum += v[i];
    }
#pragma unroll
    for (int o = 16; o; o >>= 1) sum += __shfl_xor_sync(0xffffffffu, sum, o);
    float inv = 1.f / sum;

    __syncthreads();   // all res_s reads done -> safe to overwrite as att2

    // write att to gmem + transposed row-paired att2 to smem: S[k*18 + row]
    float* ap = att + (b * 512 + n0 + w) * 512 + lane;
#pragma unroll
    for (int i = 0; i < 16; i++) {
        float av = v[i] * inv;
        ap[32 * i] = av;
        S[(lane + 32 * i) * 18 + w] = av;
    }
    __syncthreads();

    // ---- phase 3: out = att @ V ----
    // thread: split = t>>6 (kk range of 64), rr = (t>>5)&1 (rowpairs 4rr..4rr+3),
    //         d2 = t&31 (cols 2*d2, 2*d2+1)
    int split = t >> 6;
    int rr    = (t >> 5) & 1;
    int d2    = t & 31;
    const float2* V2 = (const float2*)V + (size_t)b * 512 * 32 + d2;
    const ull* att2 = (const ull*)S;                 // idx k*9 + g

    ull oacc[8];
#pragma unroll
    for (int j = 0; j < 8; j++) oacc[j] = 0ull;

    int k0 = split * 64;
#pragma unroll 8
    for (int kk = k0; kk < k0 + 64; kk++) {
        float2 vv = __ldg(V2 + kk * 32);             // coalesced 256B, L1/L2-hot
        ull vx = pk2(vv.x, vv.x);
        ull vy = pk2(vv.y, vv.y);
#pragma unroll
        for (int g4 = 0; g4 < 4; g4++) {
            ull a2 = att2[kk * 9 + rr * 4 + g4];     // broadcast LDS.64: rows {2g,2g+1}
            oacc[2 * g4]     = ffma2(a2, vx, oacc[2 * g4]);
            oacc[2 * g4 + 1] = ffma2(a2, vy, oacc[2 * g4 + 1]);
        }
    }
    __syncthreads();   // att2 reads done -> reuse S as reduction buffer

    ull* red = (ull*)S;                              // [split][512]
#pragma unroll
    for (int g4 = 0; g4 < 4; g4++) {
        int g = rr * 4 + g4;
        red[split * 512 + g * 64 + 2 * d2]     = oacc[2 * g4];
        red[split * 512 + g * 64 + 2 * d2 + 1] = oacc[2 * g4 + 1];
    }
    __syncthreads();

    // thread t reduces output float2 index t over 8 splits
    ull r = red[t];
#pragma unroll
    for (int s2 = 1; s2 < 8; s2++) r = fadd2(r, red[s2 * 512 + t]);
    float2 rv = up2(r);
    int g = t >> 6, col = t & 63;
    int nrow = b * 512 + n0 + 2 * g;
    out[nrow * 64 + col]       = rv.x;               // row 2g
    out[(nrow + 1) * 64 + col] = rv.y;               // row 2g+1
}

extern "C" void kernel_launch(void* const* d_in, const int* in_sizes, int n_in,
                              void* d_out, int out_size) {
    const float* Q  = (const float*)d_in[0];
    const float* K  = (const float*)d_in[1];
    const float* V  = (const float*)d_in[2];
    const float* W1 = (const float*)d_in[3];
    const float* b1 = (const float*)d_in[4];
    const float* W2 = (const float*)d_in[5];
    // b2 cancels in softmax

    float* out = (float*)d_out;                   // B*N*D
    float* att = (float*)d_out + BB * NN * DD;    // B*N*KL

    float* hq;  cudaGetSymbolAddress((void**)&hq,  g_hq);
    float* hkT; cudaGetSymbolAddress((void**)&hkT, g_hkT);

    kA<<<1024, 256>>>(Q, K, W1, b1, hq, hkT);
    kBC<<<128, 512>>>(hq, hkT, W2, V, att, out);
}

// round 3
// speedup vs baseline: 1.2796x; 1.2796x over previous
#include <cuda_runtime.h>
#include <cuda_bf16.h>

// MLPAttention: B=4, N=512, KLEN=512, D=64, TAU=4
//   Wq=W1[0::2], Wk=W1[1::2]; hq=Q@Wq+b1; hk=K@Wk
//   res[n,k] = sum_e relu(hq[n,e]+hk[k,e])*W2[e]   (b2 cancels in softmax)
//   relu(x)*w == 0.5*w*(x+|x|)  -> packed f32x2 with one 64-bit AND, no unpack
//   att = softmax(res/TAU); out = att@V
// Outputs: out (B*N*D) then att (B*N*K).

#define BB 4
#define NN 512
#define KL 512
#define DD 64

typedef unsigned long long ull;

__device__ float g_hq[BB * NN * DD];    // [row][e]
__device__ float g_hkT[BB * DD * KL];   // [b][e][k]

__device__ __forceinline__ ull pk2(float x, float y) {
    ull r; asm("mov.b64 %0, {%1, %2};" : "=l"(r) : "f"(x), "f"(y)); return r;
}
__device__ __forceinline__ float2 up2(ull u) {
    float2 f; asm("mov.b64 {%0, %1}, %2;" : "=f"(f.x), "=f"(f.y) : "l"(u)); return f;
}
__device__ __forceinline__ ull fadd2(ull a, ull b) {
    ull r; asm("add.rn.f32x2 %0, %1, %2;" : "=l"(r) : "l"(a), "l"(b)); return r;
}
__device__ __forceinline__ ull ffma2(ull a, ull b, ull c) {
    ull r; asm("fma.rn.f32x2 %0, %1, %2, %3;" : "=l"(r) : "l"(a), "l"(b), "l"(c)); return r;
}

// ---------- Kernel A: hq = Q@Wq + b1  and  hkT = (K@Wk)^T ----------
__global__ __launch_bounds__(256) void kA(const float* __restrict__ Q,
                                          const float* __restrict__ K,
                                          const float* __restrict__ W1,
                                          const float* __restrict__ b1,
                                          float* __restrict__ hq,
                                          float* __restrict__ hkT) {
    int t = threadIdx.x;
    if (blockIdx.x < 512) {
        __shared__ float Qs[4 * 64];
        int r0 = blockIdx.x * 4;
        Qs[t] = Q[r0 * 64 + t];
        __syncthreads();
        int rl = t >> 6, e = t & 63;
        float acc = b1[e];
#pragma unroll
        for (int d = 0; d < 64; d++)
            acc = fmaf(Qs[rl * 64 + d], __ldg(&W1[d * 128 + e]), acc);   // W1[2d][e]
        hq[(r0 + rl) * 64 + e] = acc;
    } else {
        __shared__ float Ks[64 * 65];
        int bid = blockIdx.x - 512;
        int b = bid >> 7;
        int kt = (bid >> 4) & 7;
        int et = bid & 15;
#pragma unroll
        for (int j = 0; j < 16; j++) {
            int idx = t + 256 * j;
            int kk = idx >> 6, d = idx & 63;
            Ks[kk * 65 + d] = K[(b * 512 + kt * 64 + kk) * 64 + d];
        }
        __syncthreads();
        int el = t >> 6, kl = t & 63;
        int e = et * 4 + el;
        float acc = 0.f;
#pragma unroll
        for (int d = 0; d < 64; d++)
            acc = fmaf(Ks[kl * 65 + d], __ldg(&W1[d * 128 + 64 + e]), acc);  // W1[2d+1][e]
        hkT[b * (64 * 512) + e * 512 + kt * 64 + kl] = acc;
    }
}

// ---------- Kernel BC: res -> softmax -> att, out = att@V ----------
// grid 256 (b x 64 n-tiles of 8 rows), 512 threads, 2 blocks/SM.
// S (16KB) lifecycle: res_s[8][512] -> att2 ull[4 rowpairs][512 k] -> red ull[8][256]
__global__ __launch_bounds__(512, 2) void kBC(const float* __restrict__ hq,
                                              const float* __restrict__ hkT,
                                              const float* __restrict__ W2,
                                              const float* __restrict__ V,
                                              float* __restrict__ att,
                                              float* __restrict__ out) {
    __shared__ __align__(16) float S[4096];
    __shared__ __align__(16) float hq_ff[512];   // [e][row] = e*8+row (rowpairs packed)
    __shared__ ull w2s[64];                      // {0.5*w2[e], 0.5*w2[e]}

    int b  = blockIdx.x >> 6;
    int n0 = (blockIdx.x & 63) << 3;
    int t  = threadIdx.x;

    {   // stage hq tile (gmem-coalesced)
        int row = t >> 6, e = t & 63;
        hq_ff[e * 8 + row] = hq[(b * 512 + n0 + row) * 64 + e];
    }
    if (t < 64) { float w = 0.5f * W2[t]; w2s[t] = pk2(w, w); }
    __syncthreads();

    // ---- phase 1: res[8 rows][k=t], all-packed relu via (x+|x|) ----
    const ulonglong2* hq22 = (const ulonglong2*)hq_ff;   // [e][2] — 2 rowpairs each
    const float* hkb = hkT + b * (64 * 512) + t;

    ull acc0 = 0, acc1 = 0, acc2 = 0, acc3 = 0;
#pragma unroll 8
    for (int e = 0; e < 64; e++) {
        float hkv = __ldg(hkb + e * 512);          // coalesced, L2-resident
        ull hk2 = pk2(hkv, hkv);
        ull w2e = w2s[e];
        ulonglong2 ha = hq22[e * 2];               // LDS.128 broadcast
        ulonglong2 hb = hq22[e * 2 + 1];
#define RSTEP(A, H) { ull s_ = fadd2((H), hk2); \
                      ull t_ = fadd2(s_, s_ & 0x7fffffff7fffffffULL); \
                      (A) = ffma2(t_, w2e, (A)); }
        RSTEP(acc0, ha.x) RSTEP(acc1, ha.y) RSTEP(acc2, hb.x) RSTEP(acc3, hb.y)
#undef RSTEP
    }
    {
        float2 a;
        a = up2(acc0); S[0 * 512 + t] = a.x; S[1 * 512 + t] = a.y;
        a = up2(acc1); S[2 * 512 + t] = a.x; S[3 * 512 + t] = a.y;
        a = up2(acc2); S[4 * 512 + t] = a.x; S[5 * 512 + t] = a.y;
        a = up2(acc3); S[6 * 512 + t] = a.x; S[7 * 512 + t] = a.y;
    }
    __syncthreads();

    // ---- phase 2: softmax, warps 0..7 own one row each ----
    int w = t >> 5, lane = t & 31;
    float v[16];
    float inv = 0.f;
    if (w < 8) {
        float m = -1e30f;
#pragma unroll
        for (int i = 0; i < 16; i++) {
            v[i] = S[w * 512 + lane + 32 * i];
            m = fmaxf(m, v[i]);
        }
#pragma unroll
        for (int o = 16; o; o >>= 1) m = fmaxf(m, __shfl_xor_sync(0xffffffffu, m, o));
        float sum = 0.f;
#pragma unroll
        for (int i = 0; i < 16; i++) {
            v[i] = __expf((v[i] - m) * 0.25f);     // /TAU
            sum += v[i];
        }
#pragma unroll
        for (int o = 16; o; o >>= 1) sum += __shfl_xor_sync(0xffffffffu, sum, o);
        inv = 1.f / sum;
    }
    __syncthreads();   // all res_s reads done -> safe to overwrite S as att2

    if (w < 8) {
        float* ap = att + (b * 512 + n0 + w) * 512 + lane;
        int base = (w >> 1) * 1024 + (w & 1);      // att2 ull[w>>1][k], this row = lo/hi half
#pragma unroll
        for (int i = 0; i < 16; i++) {
            float av = v[i] * inv;
            ap[32 * i] = av;                       // gmem att (coalesced)
            S[base + 2 * (lane + 32 * i)] = av;    // smem att2
        }
    }
    __syncthreads();

    // ---- phase 3: out = att @ V (split-k over 8 chunks of 64) ----
    int split = t >> 6, r6 = t & 63, rp2 = r6 >> 5, d2 = r6 & 31;
    const float2* Vb = (const float2*)V + (size_t)b * 512 * 32 + d2;
    const ull* A2 = (const ull*)S;                 // [rowpair][k]
    ull o0 = 0, o1 = 0, o2 = 0, o3 = 0;
    int k0 = split * 64;
#pragma unroll 8
    for (int kk = 0; kk < 64; kk++) {
        int k = k0 + kk;
        float2 vv = __ldg(Vb + k * 32);            // coalesced LDG.64, L2-hot
        ull vx = pk2(vv.x, vv.x);
        ull vy = pk2(vv.y, vv.y);
        ull a0 = A2[(2 * rp2) * 512 + k];          // broadcast LDS.64
        ull a1 = A2[(2 * rp2 + 1) * 512 + k];
        o0 = ffma2(a0, vx, o0);                    // rows {4rp2,4rp2+1} col 2d2
        o1 = ffma2(a0, vy, o1);                    //                   col 2d2+1
        o2 = ffma2(a1, vx, o2);                    // rows {4rp2+2,4rp2+3}
        o3 = ffma2(a1, vy, o3);
    }
    __syncthreads();   // A2 reads done -> reuse S as reduction buffer

    ull* red = (ull*)S;                            // [split][256]
    {
        int id0 = (2 * rp2) * 64 + 2 * d2;
        int id1 = (2 * rp2 + 1) * 64 + 2 * d2;
        red[split * 256 + id0]     = o0;
        red[split * 256 + id0 + 1] = o1;
        red[split * 256 + id1]     = o2;
        red[split * 256 + id1 + 1] = o3;
    }
    __syncthreads();

    if (t < 256) {
        ull r = red[t];
#pragma unroll
        for (int s2 = 1; s2 < 8; s2++) r = fadd2(r, red[s2 * 256 + t]);
        float2 rv = up2(r);
        int rp = t >> 6, c = t & 63;
        int nrow = b * 512 + n0 + 2 * rp;
        out[nrow * 64 + c]       = rv.x;
        out[(nrow + 1) * 64 + c] = rv.y;
    }
}

extern "C" void kernel_launch(void* const* d_in, const int* in_sizes, int n_in,
                              void* d_out, int out_size) {
    const float* Q  = (const float*)d_in[0];
    const float* K  = (const float*)d_in[1];
    const float* V  = (const float*)d_in[2];
    const float* W1 = (const float*)d_in[3];
    const float* b1 = (const float*)d_in[4];
    const float* W2 = (const float*)d_in[5];
    // b2 cancels in softmax

    float* out = (float*)d_out;                   // B*N*D
    float* att = (float*)d_out + BB * NN * DD;    // B*N*KL

    float* hq;  cudaGetSymbolAddress((void**)&hq,  g_hq);
    float* hkT; cudaGetSymbolAddress((void**)&hkT, g_hkT);

    kA<<<1024, 256>>>(Q, K, W1, b1, hq, hkT);
    kBC<<<256, 512>>>(hq, hkT, W2, V, att, out);
}

// round 4
// speedup vs baseline: 1.4735x; 1.1515x over previous
#include <cuda_runtime.h>
#include <cuda_bf16.h>

// MLPAttention: B=4, N=512, KLEN=512, D=64, TAU=4
//   Wq=W1[0::2], Wk=W1[1::2]; hq=Q@Wq+b1; hk=K@Wk
//   res[n,k] = sum_e relu(hq[n,e]+hk[k,e])*W2[e]   (b2 cancels in softmax)
//   relu(x)*w = 0.5*w*(x+|x|); packed over e-pairs -> horizontal add at end.
//   att = softmax(res/TAU); out = att@V
// Outputs: out (B*N*D) then att (B*N*K).

#define BB 4
#define NN 512
#define KL 512
#define DD 64

typedef unsigned long long ull;

// hk stored e-paired: float2 [b][e/2][k] = {hk[2e'][k], hk[2e'+1][k]}
__device__ float2 g_hkT2[BB * (DD / 2) * KL];

__device__ __forceinline__ ull pk2(float x, float y) {
    ull r; asm("mov.b64 %0, {%1, %2};" : "=l"(r) : "f"(x), "f"(y)); return r;
}
__device__ __forceinline__ float2 up2(ull u) {
    float2 f; asm("mov.b64 {%0, %1}, %2;" : "=f"(f.x), "=f"(f.y) : "l"(u)); return f;
}
__device__ __forceinline__ ull fadd2(ull a, ull b) {
    ull r; asm("add.rn.f32x2 %0, %1, %2;" : "=l"(r) : "l"(a), "l"(b)); return r;
}
__device__ __forceinline__ ull ffma2(ull a, ull b, ull c) {
    ull r; asm("fma.rn.f32x2 %0, %1, %2, %3;" : "=l"(r) : "l"(a), "l"(b), "l"(c)); return r;
}

// ---------- Kernel A: hkT2 = (K@Wk)^T, e-paired ----------
// grid 128: b(4) x kt(8, 64 k) x qt(4, 16 e). 256 threads: k=t&63, ei=t>>6 (4 e each).
__global__ __launch_bounds__(256) void kA(const float* __restrict__ K,
                                          const float* __restrict__ W1,
                                          float2* __restrict__ hkT2) {
    __shared__ float Ks[64 * 65];
    __shared__ float Ws[64 * 16];   // [d][eq]
    int bid = blockIdx.x;
    int b  = bid >> 5;
    int kt = (bid >> 2) & 7;
    int qt = bid & 3;
    int t = threadIdx.x;

#pragma unroll
    for (int j = 0; j < 16; j++) {
        int idx = t + 256 * j;
        int kk = idx >> 6, d = idx & 63;
        Ks[kk * 65 + d] = K[(b * 512 + kt * 64 + kk) * 64 + d];
    }
#pragma unroll
    for (int j = 0; j < 4; j++) {
        int idx = t + 256 * j;
        int d = idx >> 4, eq = idx & 15;
        Ws[idx] = W1[d * 128 + 64 + qt * 16 + eq];   // W1[2d+1][qt*16+eq]
    }
    __syncthreads();

    int k = t & 63, ei = t >> 6;
    float a0 = 0.f, a1 = 0.f, a2 = 0.f, a3 = 0.f;
#pragma unroll
    for (int d = 0; d < 64; d++) {
        float kv = Ks[k * 65 + d];                       // conflict-free (stride 65)
        float4 wv = *(const float4*)&Ws[d * 16 + ei * 4]; // broadcast LDS.128
        a0 = fmaf(kv, wv.x, a0);
        a1 = fmaf(kv, wv.y, a1);
        a2 = fmaf(kv, wv.z, a2);
        a3 = fmaf(kv, wv.w, a3);
    }
    int e0 = qt * 16 + ei * 4;                // even
    int base = b * (32 * 512) + k + kt * 0;   // k index within [0,512): kt*64 + k
    base = b * (32 * 512) + kt * 64 + k;
    hkT2[base + (e0 >> 1) * 512]       = make_float2(a0, a1);
    hkT2[base + ((e0 >> 1) + 1) * 512] = make_float2(a2, a3);
}

// ---------- Kernel BC: hq -> res -> softmax -> att, out = att@V ----------
// grid 256 (b x 64 n-tiles of 8 rows), 512 threads, 2 blocks/SM.
// S (16KB) lifecycle: Qs[8][64] (phase0, first 2KB) -> res_s[8][512]
//                     -> att2 ull[4 rowpair][512] -> red ull[8][256]
__global__ __launch_bounds__(512, 2) void kBC(const float* __restrict__ Q,
                                              const float* __restrict__ W1,
                                              const float* __restrict__ b1,
                                              const float2* __restrict__ hkT2,
                                              const float* __restrict__ W2,
                                              const float* __restrict__ V,
                                              float* __restrict__ att,
                                              float* __restrict__ out) {
    __shared__ __align__(16) float S[4096];
    __shared__ __align__(16) float hq_p[512];   // [ep][row][2] : ep*16 + row*2 + par
    __shared__ ull w2ps[32];                    // {0.5*w2[2ep], 0.5*w2[2ep+1]}

    int b  = blockIdx.x >> 6;
    int n0 = (blockIdx.x & 63) << 3;
    int t  = threadIdx.x;
    int row = t >> 6, e = t & 63;

    // ---- phase 0: hq tile (8 rows x 64 e), one output per thread ----
    S[t] = Q[(b * 512 + n0 + row) * 64 + e];    // Qs[row][e]
    if (t < 32) {
        float2 w = *(const float2*)&W2[2 * t];
        w2ps[t] = pk2(0.5f * w.x, 0.5f * w.y);
    }
    __syncthreads();
    {
        float a = __ldg(&b1[e]);
        const float* qrow = S + row * 64;
#pragma unroll
        for (int d = 0; d < 64; d++)
            a = fmaf(qrow[d], __ldg(&W1[d * 128 + e]), a);  // W1[2d][e], L1-hot
        hq_p[(e >> 1) * 16 + row * 2 + (e & 1)] = a;
    }
    __syncthreads();

    // ---- phase 1: res[8 rows][k=t], packed over e-pairs ----
    const float2* hk2b = hkT2 + b * (32 * 512) + t;
    const ulonglong2* hq22 = (const ulonglong2*)hq_p;   // [ep][4] -> rows {0,1},{2,3},...

    ull acc0 = 0, acc1 = 0, acc2 = 0, acc3 = 0, acc4 = 0, acc5 = 0, acc6 = 0, acc7 = 0;
#pragma unroll 4
    for (int ep = 0; ep < 32; ep++) {
        float2 hk = __ldg(hk2b + ep * 512);     // coalesced LDG.64, L2-resident
        ull hkp = pk2(hk.x, hk.y);
        ull w2p = w2ps[ep];
        ulonglong2 h01 = hq22[ep * 4 + 0];      // broadcast LDS.128
        ulonglong2 h23 = hq22[ep * 4 + 1];
        ulonglong2 h45 = hq22[ep * 4 + 2];
        ulonglong2 h67 = hq22[ep * 4 + 3];
#define RSTEP(A, H) { ull s_ = fadd2((H), hkp); \
                      ull u_ = fadd2(s_, s_ & 0x7fffffff7fffffffULL); \
                      (A) = ffma2(u_, w2p, (A)); }
        RSTEP(acc0, h01.x) RSTEP(acc1, h01.y) RSTEP(acc2, h23.x) RSTEP(acc3, h23.y)
        RSTEP(acc4, h45.x) RSTEP(acc5, h45.y) RSTEP(acc6, h67.x) RSTEP(acc7, h67.y)
#undef RSTEP
    }
    // horizontal add (even-e half + odd-e half) and stage res
    {
        float2 a;
        a = up2(acc0); S[0 * 512 + t] = a.x + a.y;
        a = up2(acc1); S[1 * 512 + t] = a.x + a.y;
        a = up2(acc2); S[2 * 512 + t] = a.x + a.y;
        a = up2(acc3); S[3 * 512 + t] = a.x + a.y;
        a = up2(acc4); S[4 * 512 + t] = a.x + a.y;
        a = up2(acc5); S[5 * 512 + t] = a.x + a.y;
        a = up2(acc6); S[6 * 512 + t] = a.x + a.y;
        a = up2(acc7); S[7 * 512 + t] = a.x + a.y;
    }
    __syncthreads();

    // ---- phase 2: softmax, warps 0..7 own one row each ----
    int w = t >> 5, lane = t & 31;
    float v[16];
    float inv = 0.f;
    if (w < 8) {
        float m = -1e30f;
#pragma unroll
        for (int i = 0; i < 16; i++) {
            v[i] = S[w * 512 + lane + 32 * i];
            m = fmaxf(m, v[i]);
        }
#pragma unroll
        for (int o = 16; o; o >>= 1) m = fmaxf(m, __shfl_xor_sync(0xffffffffu, m, o));
        float sum = 0.f;
#pragma unroll
        for (int i = 0; i < 16; i++) {
            v[i] = __expf((v[i] - m) * 0.25f);   // /TAU
            sum += v[i];
        }
#pragma unroll
        for (int o = 16; o; o >>= 1) sum += __shfl_xor_sync(0xffffffffu, sum, o);
        inv = 1.f / sum;
    }
    __syncthreads();   // res reads done -> S becomes att2

    if (w < 8) {
        float* ap = att + (b * 512 + n0 + w) * 512 + lane;
        int base = (w >> 1) * 1024 + (w & 1);    // ull[rowpair][k], half = w&1
#pragma unroll
        for (int i = 0; i < 16; i++) {
            float av = v[i] * inv;
            ap[32 * i] = av;                     // gmem att (coalesced)
            S[base + 2 * (lane + 32 * i)] = av;  // smem att2
        }
    }
    __syncthreads();

    // ---- phase 3: out = att @ V (split-k, 8 chunks of 64) ----
    int split = t >> 6, r6 = t & 63, rp2 = r6 >> 5, d2 = r6 & 31;
    const float2* Vb = (const float2*)V + (size_t)b * 512 * 32 + d2;
    const ull* A2 = (const ull*)S;               // [rowpair][k]
    ull o0 = 0, o1 = 0, o2 = 0, o3 = 0;
    int k0 = split * 64;
#pragma unroll 8
    for (int kk = 0; kk < 64; kk++) {
        int k = k0 + kk;
        float2 vv = __ldg(Vb + k * 32);          // coalesced LDG.64, L2-hot
        ull vx = pk2(vv.x, vv.x);
        ull vy = pk2(vv.y, vv.y);
        ull a0 = A2[(2 * rp2) * 512 + k];        // broadcast LDS.64
        ull a1 = A2[(2 * rp2 + 1) * 512 + k];
        o0 = ffma2(a0, vx, o0);
        o1 = ffma2(a0, vy, o1);
        o2 = ffma2(a1, vx, o2);
        o3 = ffma2(a1, vy, o3);
    }
    __syncthreads();   // att2 reads done -> S becomes reduction buffer

    ull* red = (ull*)S;                          // [split][256]
    {
        int id0 = (2 * rp2) * 64 + 2 * d2;
        int id1 = (2 * rp2 + 1) * 64 + 2 * d2;
        red[split * 256 + id0]     = o0;
        red[split * 256 + id0 + 1] = o1;
        red[split * 256 + id1]     = o2;
        red[split * 256 + id1 + 1] = o3;
    }
    __syncthreads();

    if (t < 256) {
        ull r = red[t];
#pragma unroll
        for (int s2 = 1; s2 < 8; s2++) r = fadd2(r, red[s2 * 256 + t]);
        float2 rv = up2(r);
        int rp = t >> 6, c = t & 63;
        int nrow = b * 512 + n0 + 2 * rp;
        out[nrow * 64 + c]       = rv.x;
        out[(nrow + 1) * 64 + c] = rv.y;
    }
}

extern "C" void kernel_launch(void* const* d_in, const int* in_sizes, int n_in,
                              void* d_out, int out_size) {
    const float* Q  = (const float*)d_in[0];
    const float* K  = (const float*)d_in[1];
    const float* V  = (const float*)d_in[2];
    const float* W1 = (const float*)d_in[3];
    const float* b1 = (const float*)d_in[4];
    const float* W2 = (const float*)d_in[5];
    // b2 cancels in softmax

    float* out = (float*)d_out;                   // B*N*D
    float* att = (float*)d_out + BB * NN * DD;    // B*N*KL

    float2* hkT2; cudaGetSymbolAddress((void**)&hkT2, g_hkT2);

    kA<<<128, 256>>>(K, W1, hkT2);
    kBC<<<256, 512>>>(Q, W1, b1, hkT2, W2, V, att, out);
}